// round 4
// baseline (speedup 1.0000x reference)
#include <cuda_runtime.h>
#include <math.h>

// kv (16,1024,259) f32, positions (16,1024,3) f32, out (16,1024,3) f32
#define BATCH     16
#define NN        1024
#define EE        128
#define CC        259          // 2*E + 3
#define TN        128          // n rows per block
#define TM        64           // m tile per iteration
#define NTHREADS  256
#define INV_SQRT_E 0.0883883476483184406f   // 1/sqrt(128)

// v2 tile: [EE/2][VS2] packed e-pairs (u64 each), m contiguous.
// VS2 even => 16B-aligned rows for LDS.128.
#define VS2       (TM + 4)     // 68 u64 = 544B rows

typedef unsigned long long u64;

__device__ __forceinline__ u64 ffma2(u64 a, u64 b, u64 c) {
    u64 d;
    asm("fma.rn.f32x2 %0, %1, %2, %3;" : "=l"(d) : "l"(a), "l"(b), "l"(c));
    return d;
}

#define SMEM_BYTES (TN*EE*4 + (EE/2)*VS2*8 + TM*3*4)

__global__ __launch_bounds__(NTHREADS, 1)
void actor_kernel(const float* __restrict__ kv,
                  const float* __restrict__ pos,
                  float* __restrict__ out)
{
    extern __shared__ float smem[];
    float* k_s  = smem;                               // [TN][EE], prescaled
    u64*   v2_s = (u64*)(smem + TN * EE);             // [EE/2][VS2] packed e-pairs
    float* pm_s = (float*)(v2_s + (EE/2) * VS2);      // [TM][3]

    const int b   = blockIdx.y;
    const int n0  = blockIdx.x * TN;
    const int tid = threadIdx.x;
    const int tx  = tid & 15;           // m-group (4 cols each)
    const int ty  = tid >> 4;           // n-group (8 rows each)

    const float* kvb  = kv  + (size_t)b * NN * CC;
    const float* posb = pos + (size_t)b * NN * 3;

    // ---- K tile once: coalesced gmem, e-contiguous smem (pairs come free) ----
    for (int idx = tid; idx < TN * EE; idx += NTHREADS) {
        int r = idx >> 7;
        int e = idx & 127;
        k_s[r * EE + e] = kvb[(size_t)(n0 + r) * CC + e] * INV_SQRT_E;
    }

    // ---- this thread's n-row positions ----
    float pnx[8], pny[8], pnz[8];
    #pragma unroll
    for (int i = 0; i < 8; i++) {
        int n = n0 + ty * 8 + i;
        pnx[i] = posb[(size_t)n * 3 + 0];
        pny[i] = posb[(size_t)n * 3 + 1];
        pnz[i] = posb[(size_t)n * 3 + 2];
    }

    float accx[8], accy[8], accz[8];
    #pragma unroll
    for (int i = 0; i < 8; i++) { accx[i] = 0.f; accy[i] = 0.f; accz[i] = 0.f; }

    // ================= main loop over m tiles =================
    for (int m0 = 0; m0 < NN; m0 += TM) {
        __syncthreads();   // previous tile consumed

        // V tile -> packed e-pair layout: v2_s[e2][m] = (v[2e2][m], v[2e2+1][m])
        for (int idx = tid; idx < TM * (EE/2); idx += NTHREADS) {
            int r  = idx >> 6;          // m local
            int e2 = idx & 63;
            const float* src = kvb + (size_t)(m0 + r) * CC + EE + 2 * e2;
            union { float2 f; u64 u; } c;
            c.f.x = src[0];
            c.f.y = src[1];
            v2_s[(size_t)e2 * VS2 + r] = c.u;
        }
        for (int idx = tid; idx < TM * 3; idx += NTHREADS)
            pm_s[idx] = posb[(size_t)m0 * 3 + idx];
        __syncthreads();

        // ---- packed S subtile: 8 n-rows x 4 m-cols, each a (even-e, odd-e) pair ----
        u64 S2[8][4];
        #pragma unroll
        for (int i = 0; i < 8; i++)
            #pragma unroll
            for (int j = 0; j < 4; j++) S2[i][j] = 0ull;

        #pragma unroll 1
        for (int e2 = 0; e2 < EE/2; e2 += 2) {   // two e-pairs (4 e) per step
            u64 ka[8][2];
            #pragma unroll
            for (int i = 0; i < 8; i++) {
                ulonglong2 t = *(const ulonglong2*)(k_s + (ty * 8 + i) * EE + e2 * 2);
                ka[i][0] = t.x; ka[i][1] = t.y;
            }
            u64 va[2][4];
            #pragma unroll
            for (int p = 0; p < 2; p++) {
                const u64* row = v2_s + (size_t)(e2 + p) * VS2 + tx * 4;
                ulonglong2 t0 = *(const ulonglong2*)(row);
                ulonglong2 t1 = *(const ulonglong2*)(row + 2);
                va[p][0] = t0.x; va[p][1] = t0.y; va[p][2] = t1.x; va[p][3] = t1.y;
            }
            #pragma unroll
            for (int i = 0; i < 8; i++)
                #pragma unroll
                for (int p = 0; p < 2; p++)
                    #pragma unroll
                    for (int j = 0; j < 4; j++)
                        S2[i][j] = ffma2(ka[i][p], va[p][j], S2[i][j]);
        }

        // ---- fused epilogue ----
        #pragma unroll
        for (int j = 0; j < 4; j++) {
            int ml = tx * 4 + j;
            float pmx = pm_s[ml * 3 + 0];
            float pmy = pm_s[ml * 3 + 1];
            float pmz = pm_s[ml * 3 + 2];
            #pragma unroll
            for (int i = 0; i < 8; i++) {
                union { u64 u; float2 f; } c; c.u = S2[i][j];
                float s = c.f.x + c.f.y;            // fold even/odd-e halves
                float dx = pnx[i] - pmx;
                float dy = pny[i] - pmy;
                float dz = pnz[i] - pmz;
                float sq = fmaf(dx, dx, fmaf(dy, dy, fmaf(dz, dz, 1e-30f)));
                float w  = s * rsqrtf(sq);          // diagonal: 0 * finite = 0
                accx[i] = fmaf(dx, w, accx[i]);
                accy[i] = fmaf(dy, w, accy[i]);
                accz[i] = fmaf(dz, w, accz[i]);
            }
        }
    }

    // ---- reduce 16 tx-slices ----
    #pragma unroll
    for (int off = 8; off >= 1; off >>= 1) {
        #pragma unroll
        for (int i = 0; i < 8; i++) {
            accx[i] += __shfl_xor_sync(0xffffffffu, accx[i], off);
            accy[i] += __shfl_xor_sync(0xffffffffu, accy[i], off);
            accz[i] += __shfl_xor_sync(0xffffffffu, accz[i], off);
        }
    }

    if (tx == 0) {
        #pragma unroll
        for (int i = 0; i < 8; i++) {
            int n = n0 + ty * 8 + i;
            float* o = out + ((size_t)b * NN + n) * 3;
            o[0] = 0.01f * tanhf(accx[i]);
            o[1] = 0.01f * tanhf(accy[i]);
            o[2] = 0.01f * tanhf(accz[i]);
        }
    }
}

extern "C" void kernel_launch(void* const* d_in, const int* in_sizes, int n_in,
                              void* d_out, int out_size)
{
    const float* kv  = (const float*)d_in[0];
    const float* pos = (const float*)d_in[1];
    float* out = (float*)d_out;
    (void)in_sizes; (void)n_in; (void)out_size;

    cudaFuncSetAttribute(actor_kernel,
                         cudaFuncAttributeMaxDynamicSharedMemorySize, SMEM_BYTES);

    dim3 grid(NN / TN, BATCH);   // 128 blocks
    actor_kernel<<<grid, NTHREADS, SMEM_BYTES>>>(kv, pos, out);
}

// round 7
// speedup vs baseline: 2.3612x; 2.3612x over previous
#include <cuda_runtime.h>
#include <cuda_bf16.h>
#include <cstdint>
#include <math.h>

// kv (16,1024,259) f32, positions (16,1024,3) f32, out (16,1024,3) f32
#define BATCH     16
#define NN        1024
#define EE        128
#define CC        259
#define TN        128          // n rows per block
#define TM        64           // m cols per tile
#define NT        (NN / TM)    // 16 tiles
#define NTHREADS  256
#define INV_SQRT_E 0.0883883476483184406f

// smem rows: 128 bf16 + 8 pad = 272 B (17 x 16B -> ldmatrix conflict-free)
#define ROWB      272
#define OFF_POS   0
#define POS_BYTES (NN * 3 * 4)               // 12288
#define OFF_KHI   (OFF_POS + POS_BYTES)      // 12288
#define KMAT      (TN * ROWB)                // 34816
#define OFF_KLO   (OFF_KHI + KMAT)           // 47104
#define OFF_V     (OFF_KLO + KMAT)           // 81920
#define VMAT      (TM * ROWB)                // 17408
#define VBUF      (2 * VMAT)                 // vhi + vlo = 34816
#define SMEM_TOTAL (OFF_V + 2 * VBUF)        // 151552 B

// ---------------- PTX helpers ----------------
__device__ __forceinline__ uint32_t smem_u32(const void* p) {
    uint32_t a;
    asm("{ .reg .u64 t; cvta.to.shared.u64 t, %1; cvt.u32.u64 %0, t; }" : "=r"(a) : "l"(p));
    return a;
}
__device__ __forceinline__ void ldsm4(uint32_t* r, uint32_t addr) {
    asm volatile("ldmatrix.sync.aligned.m8n8.x4.shared.b16 {%0,%1,%2,%3}, [%4];"
                 : "=r"(r[0]), "=r"(r[1]), "=r"(r[2]), "=r"(r[3]) : "r"(addr));
}
__device__ __forceinline__ void mma_bf16(float* d, const uint32_t* a, uint32_t b0, uint32_t b1) {
    asm volatile(
        "mma.sync.aligned.m16n8k16.row.col.f32.bf16.bf16.f32 "
        "{%0,%1,%2,%3}, {%4,%5,%6,%7}, {%8,%9}, {%0,%1,%2,%3};"
        : "+f"(d[0]), "+f"(d[1]), "+f"(d[2]), "+f"(d[3])
        : "r"(a[0]), "r"(a[1]), "r"(a[2]), "r"(a[3]), "r"(b0), "r"(b1));
}
// split x into bf16 hi + bf16 lo (lo = bf16(x - float(hi)))
__device__ __forceinline__ void split2(float x0, float x1, uint32_t& hi, uint32_t& lo) {
    __nv_bfloat16 h0 = __float2bfloat16(x0), h1 = __float2bfloat16(x1);
    __nv_bfloat16 l0 = __float2bfloat16(x0 - __bfloat162float(h0));
    __nv_bfloat16 l1 = __float2bfloat16(x1 - __bfloat162float(h1));
    hi = (uint32_t)__bfloat16_as_ushort(h0) | ((uint32_t)__bfloat16_as_ushort(h1) << 16);
    lo = (uint32_t)__bfloat16_as_ushort(l0) | ((uint32_t)__bfloat16_as_ushort(l1) << 16);
}

__global__ __launch_bounds__(NTHREADS, 1)
void actor_mma_kernel(const float* __restrict__ kv,
                      const float* __restrict__ pos,
                      float* __restrict__ out)
{
    extern __shared__ char smem[];
    const uint32_t sb = smem_u32(smem);
    float* pos_s = (float*)(smem + OFF_POS);

    const int tid  = threadIdx.x;
    const int w    = tid >> 5;
    const int lane = tid & 31;
    const int b    = blockIdx.y;
    const int n0   = blockIdx.x * TN;

    const float* kvb  = kv  + (size_t)b * NN * CC;
    const float* posb = pos + (size_t)b * NN * 3;

    // ---- stage all m positions ----
    for (int i = tid; i < NN * 3; i += NTHREADS) pos_s[i] = posb[i];

    // ---- stage K (prescaled), split hi/lo ----
    for (int q = tid; q < TN * 32; q += NTHREADS) {      // 32 float4-groups/row
        int r = q >> 5, c4 = q & 31;
        const float* src = kvb + (size_t)(n0 + r) * CC + c4 * 4;
        float x0 = src[0] * INV_SQRT_E, x1 = src[1] * INV_SQRT_E;
        float x2 = src[2] * INV_SQRT_E, x3 = src[3] * INV_SQRT_E;
        uint32_t h01, l01, h23, l23;
        split2(x0, x1, h01, l01);
        split2(x2, x3, h23, l23);
        uint32_t off = (uint32_t)r * ROWB + (uint32_t)c4 * 8;
        *(uint2*)(smem + OFF_KHI + off) = make_uint2(h01, h23);
        *(uint2*)(smem + OFF_KLO + off) = make_uint2(l01, l23);
    }

    // ---- stage V tile 0 ----
    for (int q = tid; q < TM * 32; q += NTHREADS) {
        int r = q >> 5, c4 = q & 31;
        const float* src = kvb + (size_t)r * CC + EE + c4 * 4;
        uint32_t h01, l01, h23, l23;
        split2(src[0], src[1], h01, l01);
        split2(src[2], src[3], h23, l23);
        uint32_t off = (uint32_t)r * ROWB + (uint32_t)c4 * 8;
        *(uint2*)(smem + OFF_V + off)        = make_uint2(h01, h23);
        *(uint2*)(smem + OFF_V + VMAT + off) = make_uint2(l01, l23);
    }
    __syncthreads();

    // ---- per-thread n-row state (2 rows) ----
    const int r0loc = w * 16 + (lane >> 2);       // local n row; second = +8
    const float pn0x = posb[(size_t)(n0 + r0loc) * 3 + 0];
    const float pn0y = posb[(size_t)(n0 + r0loc) * 3 + 1];
    const float pn0z = posb[(size_t)(n0 + r0loc) * 3 + 2];
    const float pn1x = posb[(size_t)(n0 + r0loc + 8) * 3 + 0];
    const float pn1y = posb[(size_t)(n0 + r0loc + 8) * 3 + 1];
    const float pn1z = posb[(size_t)(n0 + r0loc + 8) * 3 + 2];
    float a0x = 0.f, a0y = 0.f, a0z = 0.f, a1x = 0.f, a1y = 0.f, a1z = 0.f;

    // ldmatrix lane address components
    const uint32_t a_row  = (uint32_t)(w * 16 + (lane & 15));
    const uint32_t a_coff = (uint32_t)(lane >> 4) * 16;
    const uint32_t b_row  = (uint32_t)((lane & 7) + ((lane >> 4) & 1) * 8);
    const uint32_t b_coff = (uint32_t)((lane >> 3) & 1) * 16;
    const uint32_t a_hi_base = sb + OFF_KHI + a_row * ROWB + a_coff;
    const uint32_t a_lo_base = sb + OFF_KLO + a_row * ROWB + a_coff;

    for (int t = 0; t < NT; t++) {
        // prefetch next V tile into registers (scalar: CC=259 kills alignment)
        float vreg[32];
        if (t + 1 < NT) {
            const float* vsrc = kvb + (size_t)(t + 1) * TM * CC + EE;
            #pragma unroll
            for (int i = 0; i < 8; i++) {
                int q = i * NTHREADS + tid;        // 0..2047
                int r = q >> 5, c4 = q & 31;
                const float* s = vsrc + (size_t)r * CC + c4 * 4;
                vreg[i * 4 + 0] = s[0]; vreg[i * 4 + 1] = s[1];
                vreg[i * 4 + 2] = s[2]; vreg[i * 4 + 3] = s[3];
            }
        }

        const uint32_t vb    = sb + OFF_V + (uint32_t)(t & 1) * VBUF;
        const uint32_t b_hi0 = vb + b_row * ROWB + b_coff;
        const uint32_t b_lo0 = b_hi0 + VMAT;

        float acc[8][4];
        #pragma unroll
        for (int i = 0; i < 8; i++)
            #pragma unroll
            for (int j = 0; j < 4; j++) acc[i][j] = 0.f;

        #pragma unroll
        for (int k = 0; k < 8; k++) {             // e chunks of 16
            uint32_t ahi[4], alo[4];
            ldsm4(ahi, a_hi_base + (uint32_t)k * 32);
            ldsm4(alo, a_lo_base + (uint32_t)k * 32);
            #pragma unroll
            for (int p = 0; p < 4; p++) {         // n-pairs of 16 m-cols
                uint32_t bhi[4], blo[4];
                uint32_t boff = (uint32_t)p * 16 * ROWB + (uint32_t)k * 32;
                ldsm4(bhi, b_hi0 + boff);
                ldsm4(blo, b_lo0 + boff);
                mma_bf16(acc[2*p],     ahi, bhi[0], bhi[1]);   // hi*hi
                mma_bf16(acc[2*p + 1], ahi, bhi[2], bhi[3]);
                mma_bf16(acc[2*p],     ahi, blo[0], blo[1]);   // hi*lo
                mma_bf16(acc[2*p + 1], ahi, blo[2], blo[3]);
                mma_bf16(acc[2*p],     alo, bhi[0], bhi[1]);   // lo*hi
                mma_bf16(acc[2*p + 1], alo, bhi[2], bhi[3]);
            }
        }

        // store prefetched V into the other buffer
        if (t + 1 < NT) {
            char* dst = smem + OFF_V + ((t + 1) & 1) * VBUF;
            #pragma unroll
            for (int i = 0; i < 8; i++) {
                int q = i * NTHREADS + tid;
                int r = q >> 5, c4 = q & 31;
                uint32_t h01, l01, h23, l23;
                split2(vreg[i*4+0], vreg[i*4+1], h01, l01);
                split2(vreg[i*4+2], vreg[i*4+3], h23, l23);
                uint32_t off = (uint32_t)r * ROWB + (uint32_t)c4 * 8;
                *(uint2*)(dst + off)        = make_uint2(h01, h23);
                *(uint2*)(dst + VMAT + off) = make_uint2(l01, l23);
            }
        }

        // ---- fused epilogue on this tile's S fragments ----
        const int mbase = t * TM;
        #pragma unroll
        for (int bi = 0; bi < 8; bi++) {
            #pragma unroll
            for (int cc = 0; cc < 2; cc++) {
                int ml = bi * 8 + (lane & 3) * 2 + cc;
                const float* pm = pos_s + (mbase + ml) * 3;
                float pmx = pm[0], pmy = pm[1], pmz = pm[2];
                // row r0loc
                {
                    float dx = pn0x - pmx, dy = pn0y - pmy, dz = pn0z - pmz;
                    float sq = fmaf(dx, dx, fmaf(dy, dy, fmaf(dz, dz, 1e-30f)));
                    float wg = acc[bi][cc] * rsqrtf(sq);     // diagonal: 0*finite=0
                    a0x = fmaf(dx, wg, a0x); a0y = fmaf(dy, wg, a0y); a0z = fmaf(dz, wg, a0z);
                }
                // row r0loc + 8
                {
                    float dx = pn1x - pmx, dy = pn1y - pmy, dz = pn1z - pmz;
                    float sq = fmaf(dx, dx, fmaf(dy, dy, fmaf(dz, dz, 1e-30f)));
                    float wg = acc[bi][2 + cc] * rsqrtf(sq);
                    a1x = fmaf(dx, wg, a1x); a1y = fmaf(dy, wg, a1y); a1z = fmaf(dz, wg, a1z);
                }
            }
        }
        __syncthreads();
    }

    // ---- reduce across the 4 lanes of each quad (same rows, different m-cols) ----
    #pragma unroll
    for (int off = 1; off <= 2; off <<= 1) {
        a0x += __shfl_xor_sync(0xffffffffu, a0x, off);
        a0y += __shfl_xor_sync(0xffffffffu, a0y, off);
        a0z += __shfl_xor_sync(0xffffffffu, a0z, off);
        a1x += __shfl_xor_sync(0xffffffffu, a1x, off);
        a1y += __shfl_xor_sync(0xffffffffu, a1y, off);
        a1z += __shfl_xor_sync(0xffffffffu, a1z, off);
    }
    if ((lane & 3) == 0) {
        float* o0 = out + ((size_t)b * NN + n0 + r0loc) * 3;
        o0[0] = 0.01f * tanhf(a0x);
        o0[1] = 0.01f * tanhf(a0y);
        o0[2] = 0.01f * tanhf(a0z);
        float* o1 = out + ((size_t)b * NN + n0 + r0loc + 8) * 3;
        o1[0] = 0.01f * tanhf(a1x);
        o1[1] = 0.01f * tanhf(a1y);
        o1[2] = 0.01f * tanhf(a1z);
    }
}

extern "C" void kernel_launch(void* const* d_in, const int* in_sizes, int n_in,
                              void* d_out, int out_size)
{
    const float* kv  = (const float*)d_in[0];
    const float* pos = (const float*)d_in[1];
    float* out = (float*)d_out;
    (void)in_sizes; (void)n_in; (void)out_size;

    cudaFuncSetAttribute(actor_mma_kernel,
                         cudaFuncAttributeMaxDynamicSharedMemorySize, SMEM_TOTAL);

    dim3 grid(NN / TN, BATCH);   // (8,16) = 128 blocks
    actor_mma_kernel<<<grid, NTHREADS, SMEM_TOTAL>>>(kv, pos, out);
}

// round 8
// speedup vs baseline: 2.3988x; 1.0159x over previous
#include <cuda_runtime.h>
#include <cuda_bf16.h>
#include <cstdint>
#include <math.h>

// kv (16,1024,259) f32, positions (16,1024,3) f32, out (16,1024,3) f32
#define BATCH     16
#define NN        1024
#define EE        128
#define CC        259
#define TN        128          // n rows per block
#define TM        64           // m cols per tile
#define NT        (NN / TM)    // 16 tiles
#define NTHREADS  256
#define INV_SQRT_E 0.0883883476483184406f

// smem rows: 128 bf16 + 8 pad = 272 B (17 x 16B -> ldmatrix conflict-free)
#define ROWB      272
#define OFF_POS   0
#define POS_BYTES (NN * 3 * 4)               // 12288
#define OFF_KHI   (OFF_POS + POS_BYTES)      // 12288
#define KMAT      (TN * ROWB)                // 34816
#define OFF_KLO   (OFF_KHI + KMAT)           // 47104
#define OFF_V     (OFF_KLO + KMAT)           // 81920
#define VMAT      (TM * ROWB)                // 17408
#define VBUF      (2 * VMAT)                 // vhi + vlo = 34816
#define SMEM_TOTAL (OFF_V + 2 * VBUF)        // 151552 B

// ---------------- PTX helpers ----------------
__device__ __forceinline__ uint32_t smem_u32(const void* p) {
    uint32_t a;
    asm("{ .reg .u64 t; cvta.to.shared.u64 t, %1; cvt.u32.u64 %0, t; }" : "=r"(a) : "l"(p));
    return a;
}
__device__ __forceinline__ void ldsm4(uint32_t* r, uint32_t addr) {
    asm volatile("ldmatrix.sync.aligned.m8n8.x4.shared.b16 {%0,%1,%2,%3}, [%4];"
                 : "=r"(r[0]), "=r"(r[1]), "=r"(r[2]), "=r"(r[3]) : "r"(addr));
}
__device__ __forceinline__ void mma_bf16(float* d, const uint32_t* a, uint32_t b0, uint32_t b1) {
    asm volatile(
        "mma.sync.aligned.m16n8k16.row.col.f32.bf16.bf16.f32 "
        "{%0,%1,%2,%3}, {%4,%5,%6,%7}, {%8,%9}, {%0,%1,%2,%3};"
        : "+f"(d[0]), "+f"(d[1]), "+f"(d[2]), "+f"(d[3])
        : "r"(a[0]), "r"(a[1]), "r"(a[2]), "r"(a[3]), "r"(b0), "r"(b1));
}
// split x into bf16 hi + bf16 lo (lo = bf16(x - float(hi)))
__device__ __forceinline__ void split2(float x0, float x1, uint32_t& hi, uint32_t& lo) {
    __nv_bfloat16 h0 = __float2bfloat16(x0), h1 = __float2bfloat16(x1);
    __nv_bfloat16 l0 = __float2bfloat16(x0 - __bfloat162float(h0));
    __nv_bfloat16 l1 = __float2bfloat16(x1 - __bfloat162float(h1));
    hi = (uint32_t)__bfloat16_as_ushort(h0) | ((uint32_t)__bfloat16_as_ushort(h1) << 16);
    lo = (uint32_t)__bfloat16_as_ushort(l0) | ((uint32_t)__bfloat16_as_ushort(l1) << 16);
}

__global__ __launch_bounds__(NTHREADS, 1)
void actor_mma_kernel(const float* __restrict__ kv,
                      const float* __restrict__ pos,
                      float* __restrict__ out)
{
    extern __shared__ char smem[];
    const uint32_t sb = smem_u32(smem);
    float* pos_s = (float*)(smem + OFF_POS);

    const int tid  = threadIdx.x;
    const int w    = tid >> 5;
    const int lane = tid & 31;
    const int b    = blockIdx.y;
    const int n0   = blockIdx.x * TN;

    const float* kvb  = kv  + (size_t)b * NN * CC;
    const float* posb = pos + (size_t)b * NN * 3;

    // ---- stage all m positions ----
    for (int i = tid; i < NN * 3; i += NTHREADS) pos_s[i] = posb[i];

    // ---- stage K (prescaled), split hi/lo ----
    for (int q = tid; q < TN * 32; q += NTHREADS) {      // 32 float4-groups/row
        int r = q >> 5, c4 = q & 31;
        const float* src = kvb + (size_t)(n0 + r) * CC + c4 * 4;
        float x0 = src[0] * INV_SQRT_E, x1 = src[1] * INV_SQRT_E;
        float x2 = src[2] * INV_SQRT_E, x3 = src[3] * INV_SQRT_E;
        uint32_t h01, l01, h23, l23;
        split2(x0, x1, h01, l01);
        split2(x2, x3, h23, l23);
        uint32_t off = (uint32_t)r * ROWB + (uint32_t)c4 * 8;
        *(uint2*)(smem + OFF_KHI + off) = make_uint2(h01, h23);
        *(uint2*)(smem + OFF_KLO + off) = make_uint2(l01, l23);
    }

    // ---- stage V tile 0 ----
    for (int q = tid; q < TM * 32; q += NTHREADS) {
        int r = q >> 5, c4 = q & 31;
        const float* src = kvb + (size_t)r * CC + EE + c4 * 4;
        uint32_t h01, l01, h23, l23;
        split2(src[0], src[1], h01, l01);
        split2(src[2], src[3], h23, l23);
        uint32_t off = (uint32_t)r * ROWB + (uint32_t)c4 * 8;
        *(uint2*)(smem + OFF_V + off)        = make_uint2(h01, h23);
        *(uint2*)(smem + OFF_V + VMAT + off) = make_uint2(l01, l23);
    }
    __syncthreads();

    // ---- per-thread n-row state (2 rows) ----
    const int r0loc = w * 16 + (lane >> 2);       // local n row; second = +8
    const float pn0x = posb[(size_t)(n0 + r0loc) * 3 + 0];
    const float pn0y = posb[(size_t)(n0 + r0loc) * 3 + 1];
    const float pn0z = posb[(size_t)(n0 + r0loc) * 3 + 2];
    const float pn1x = posb[(size_t)(n0 + r0loc + 8) * 3 + 0];
    const float pn1y = posb[(size_t)(n0 + r0loc + 8) * 3 + 1];
    const float pn1z = posb[(size_t)(n0 + r0loc + 8) * 3 + 2];
    float a0x = 0.f, a0y = 0.f, a0z = 0.f, a1x = 0.f, a1y = 0.f, a1z = 0.f;

    // ldmatrix lane address components
    const uint32_t a_row  = (uint32_t)(w * 16 + (lane & 15));
    const uint32_t a_coff = (uint32_t)(lane >> 4) * 16;
    const uint32_t b_row  = (uint32_t)((lane & 7) + ((lane >> 4) & 1) * 8);
    const uint32_t b_coff = (uint32_t)((lane >> 3) & 1) * 16;
    const uint32_t a_hi_base = sb + OFF_KHI + a_row * ROWB + a_coff;
    const uint32_t a_lo_base = sb + OFF_KLO + a_row * ROWB + a_coff;

    for (int t = 0; t < NT; t++) {
        // prefetch next V tile into registers (scalar: CC=259 kills alignment)
        float vreg[32];
        if (t + 1 < NT) {
            const float* vsrc = kvb + (size_t)(t + 1) * TM * CC + EE;
            #pragma unroll
            for (int i = 0; i < 8; i++) {
                int q = i * NTHREADS + tid;        // 0..2047
                int r = q >> 5, c4 = q & 31;
                const float* s = vsrc + (size_t)r * CC + c4 * 4;
                vreg[i * 4 + 0] = s[0]; vreg[i * 4 + 1] = s[1];
                vreg[i * 4 + 2] = s[2]; vreg[i * 4 + 3] = s[3];
            }
        }

        const uint32_t vb    = sb + OFF_V + (uint32_t)(t & 1) * VBUF;
        const uint32_t b_hi0 = vb + b_row * ROWB + b_coff;
        const uint32_t b_lo0 = b_hi0 + VMAT;

        float acc[8][4];
        #pragma unroll
        for (int i = 0; i < 8; i++)
            #pragma unroll
            for (int j = 0; j < 4; j++) acc[i][j] = 0.f;

        #pragma unroll
        for (int k = 0; k < 8; k++) {             // e chunks of 16
            uint32_t ahi[4], alo[4];
            ldsm4(ahi, a_hi_base + (uint32_t)k * 32);
            ldsm4(alo, a_lo_base + (uint32_t)k * 32);
            #pragma unroll
            for (int p = 0; p < 4; p++) {         // n-pairs of 16 m-cols
                uint32_t bhi[4], blo[4];
                uint32_t boff = (uint32_t)p * 16 * ROWB + (uint32_t)k * 32;
                ldsm4(bhi, b_hi0 + boff);
                ldsm4(blo, b_lo0 + boff);
                mma_bf16(acc[2*p],     ahi, bhi[0], bhi[1]);   // hi*hi
                mma_bf16(acc[2*p + 1], ahi, bhi[2], bhi[3]);
                mma_bf16(acc[2*p],     ahi, blo[0], blo[1]);   // hi*lo
                mma_bf16(acc[2*p + 1], ahi, blo[2], blo[3]);
                mma_bf16(acc[2*p],     alo, bhi[0], bhi[1]);   // lo*hi
                mma_bf16(acc[2*p + 1], alo, bhi[2], bhi[3]);
            }
        }

        // store prefetched V into the other buffer
        if (t + 1 < NT) {
            char* dst = smem + OFF_V + ((t + 1) & 1) * VBUF;
            #pragma unroll
            for (int i = 0; i < 8; i++) {
                int q = i * NTHREADS + tid;
                int r = q >> 5, c4 = q & 31;
                uint32_t h01, l01, h23, l23;
                split2(vreg[i*4+0], vreg[i*4+1], h01, l01);
                split2(vreg[i*4+2], vreg[i*4+3], h23, l23);
                uint32_t off = (uint32_t)r * ROWB + (uint32_t)c4 * 8;
                *(uint2*)(dst + off)        = make_uint2(h01, h23);
                *(uint2*)(dst + VMAT + off) = make_uint2(l01, l23);
            }
        }

        // ---- fused epilogue on this tile's S fragments ----
        const int mbase = t * TM;
        #pragma unroll
        for (int bi = 0; bi < 8; bi++) {
            #pragma unroll
            for (int cc = 0; cc < 2; cc++) {
                int ml = bi * 8 + (lane & 3) * 2 + cc;
                const float* pm = pos_s + (mbase + ml) * 3;
                float pmx = pm[0], pmy = pm[1], pmz = pm[2];
                // row r0loc
                {
                    float dx = pn0x - pmx, dy = pn0y - pmy, dz = pn0z - pmz;
                    float sq = fmaf(dx, dx, fmaf(dy, dy, fmaf(dz, dz, 1e-30f)));
                    float wg = acc[bi][cc] * rsqrtf(sq);     // diagonal: 0*finite=0
                    a0x = fmaf(dx, wg, a0x); a0y = fmaf(dy, wg, a0y); a0z = fmaf(dz, wg, a0z);
                }
                // row r0loc + 8
                {
                    float dx = pn1x - pmx, dy = pn1y - pmy, dz = pn1z - pmz;
                    float sq = fmaf(dx, dx, fmaf(dy, dy, fmaf(dz, dz, 1e-30f)));
                    float wg = acc[bi][2 + cc] * rsqrtf(sq);
                    a1x = fmaf(dx, wg, a1x); a1y = fmaf(dy, wg, a1y); a1z = fmaf(dz, wg, a1z);
                }
            }
        }
        __syncthreads();
    }

    // ---- reduce across the 4 lanes of each quad (same rows, different m-cols) ----
    #pragma unroll
    for (int off = 1; off <= 2; off <<= 1) {
        a0x += __shfl_xor_sync(0xffffffffu, a0x, off);
        a0y += __shfl_xor_sync(0xffffffffu, a0y, off);
        a0z += __shfl_xor_sync(0xffffffffu, a0z, off);
        a1x += __shfl_xor_sync(0xffffffffu, a1x, off);
        a1y += __shfl_xor_sync(0xffffffffu, a1y, off);
        a1z += __shfl_xor_sync(0xffffffffu, a1z, off);
    }
    if ((lane & 3) == 0) {
        float* o0 = out + ((size_t)b * NN + n0 + r0loc) * 3;
        o0[0] = 0.01f * tanhf(a0x);
        o0[1] = 0.01f * tanhf(a0y);
        o0[2] = 0.01f * tanhf(a0z);
        float* o1 = out + ((size_t)b * NN + n0 + r0loc + 8) * 3;
        o1[0] = 0.01f * tanhf(a1x);
        o1[1] = 0.01f * tanhf(a1y);
        o1[2] = 0.01f * tanhf(a1z);
    }
}

extern "C" void kernel_launch(void* const* d_in, const int* in_sizes, int n_in,
                              void* d_out, int out_size)
{
    const float* kv  = (const float*)d_in[0];
    const float* pos = (const float*)d_in[1];
    float* out = (float*)d_out;
    (void)in_sizes; (void)n_in; (void)out_size;

    cudaFuncSetAttribute(actor_mma_kernel,
                         cudaFuncAttributeMaxDynamicSharedMemorySize, SMEM_TOTAL);

    dim3 grid(NN / TN, BATCH);   // (8,16) = 128 blocks
    actor_mma_kernel<<<grid, NTHREADS, SMEM_TOTAL>>>(kv, pos, out);
}